// round 9
// baseline (speedup 1.0000x reference)
#include <cuda_runtime.h>
#include <cstdint>

// T=4 tables, E=1,000,000 rows/table, D=128 dims, B=8192 bags, L=32 bag length
// indices: [T, B, L] (int32 OR int64 — detected inline per warp)
// weights: fp32 [T, E, D]; output: fp32 [B, T*D]
// out[b, t*D + d] = sum_l weights[t, indices[t,b,l], d]
//
// Perf model (R2-R8 measured): DRAM traffic is at the dedup minimum (~500MB);
// throughput pins at 6302 GB/s = the B300 path-independent LTS chip cap
// (~6300 B/cyc). Kernel is AT the floor (79.4us). Winning config: 256-thread
// blocks, warp-per-bag, phase-locked t-loop with __syncthreads(), index-load
// software pipelining, warp-local dtype probe, streaming idx/out.
// This round: dead-work polish only (skip t=3 prefetch, skip final barrier,
// max-L1 carveout).

#define T_TABLES 4
#define E_ROWS   1000000
#define D_DIM    128
#define B_BATCH  8192
#define L_BAG    32

// Index dtype detected per warp: every warp reads idx[0..31] as an int64 view
// (same 256B line chip-wide -> L2 hit). True int64 data (row ids < 1M) passes
// the range check on all lanes; int32 data viewed as int64 has random row-ids
// in the hi-words, so P(all 32 pass) ~= (1e-6)^32 ~ 0.
__global__ __launch_bounds__(256) void embbag_kernel(
    const void*  __restrict__ indices_raw,   // [T*B*L] int32 or int64
    const float* __restrict__ weights,       // [T*E*D]
    float*       __restrict__ out)           // [B*T*D]
{
    const int lane = threadIdx.x & 31;
    const int b    = blockIdx.x * 8 + (threadIdx.x >> 5);   // 0..8191, exact

    // Warp-local dtype probe (no barrier, no smem).
    const long long pv = __ldg(((const long long*)indices_raw) + lane);
    const unsigned bad = __ballot_sync(0xffffffffu, pv < 0 || pv >= E_ROWS);
    const int is64 = (bad == 0u) ? 1 : 0;

    const float4* __restrict__ wf4 = reinterpret_cast<const float4*>(weights);
    float4* __restrict__ of4 =
        reinterpret_cast<float4*>(out) + (size_t)b * (T_TABLES * D_DIM / 4);

    // Coalesced streaming load of this warp's 32 bag indices for table t.
    auto load_bag = [&](int t) -> long long {
        const size_t off = ((size_t)t * B_BATCH + b) * L_BAG + lane;
        return is64 ? __ldcs(((const long long*)indices_raw) + off)
                    : (long long)__ldcs(((const int*)indices_raw) + off);
    };

    long long my_idx = load_bag(0);

    #pragma unroll 1
    for (int t = 0; t < T_TABLES; ++t) {
        // Prefetch next table's indices; latency hides behind the 32 gathers.
        long long next_idx = 0;
        if (t < T_TABLES - 1) next_idx = load_bag(t + 1);

        const float4* __restrict__ wbase = wf4 + (size_t)t * E_ROWS * (D_DIM / 4);

        float4 acc = make_float4(0.f, 0.f, 0.f, 0.f);
        #pragma unroll
        for (int l = 0; l < L_BAG; ++l) {
            const long long row = __shfl_sync(0xffffffffu, my_idx, l);
            const float4 v = __ldg(wbase + (size_t)row * (D_DIM / 4) + lane);
            acc.x += v.x; acc.y += v.y; acc.z += v.z; acc.w += v.w;
        }

        // Streaming store: output is never re-read; don't pollute L2.
        __stcs(of4 + t * (D_DIM / 4) + lane, acc);

        // Keep the block phase-aligned on the same table for L2 locality.
        // (No barrier after the last phase — nothing left to align.)
        if (t < T_TABLES - 1) __syncthreads();

        my_idx = next_idx;
    }
}

extern "C" void kernel_launch(void* const* d_in, const int* in_sizes, int n_in,
                              void* d_out, int out_size)
{
    // Identify inputs by element count (robust to metadata ordering):
    // indices: T*B*L = 1,048,576 ; weights: T*E*D = 512,000,000
    const void*  indices = d_in[0];
    const float* weights = (const float*)d_in[1];
    if (n_in >= 2) {
        long long s0 = in_sizes[0], s1 = in_sizes[1];
        if (s0 > s1) {
            weights = (const float*)d_in[0];
            indices = d_in[1];
        }
    }
    float* out = (float*)d_out;

    // Kernel uses no static smem: give L1D the full carveout (one-time,
    // graph-capture-safe attribute set; idempotent across replays).
    static bool carveout_done = false;
    if (!carveout_done) {
        cudaFuncSetAttribute(embbag_kernel,
                             cudaFuncAttributePreferredSharedMemoryCarveout, 0);
        carveout_done = true;
    }

    const int blocks  = B_BATCH / 8;   // 1024 blocks x 8 warps = 8192 warps, 1 wave
    const int threads = 256;
    embbag_kernel<<<blocks, threads>>>(indices, weights, out);
}